// round 10
// baseline (speedup 1.0000x reference)
#include <cuda_runtime.h>
#include <cuda_bf16.h>
#include <cstdint>

#define BB 4
#define SS 2048
#define DD 512
#define HH 8
#define MTOK (BB*SS)
#define QKVD 1536
#define QSCALE (0.125f * 1.44269504f)   // 1/sqrt(dk) * log2(e)

// Scratch (module-load allocated; no cudaMalloc anywhere)
__device__ __align__(256) __nv_bfloat16 g_x16[MTOK*DD];
__device__ __align__(256) __nv_bfloat16 g_wqkv[QKVD*DD];
__device__ __align__(256) __nv_bfloat16 g_wo[DD*DD];
__device__ __align__(256) __nv_bfloat16 g_qkv[MTOK*QKVD];
__device__ __align__(256) __nv_bfloat16 g_ctx[MTOK*DD];
__device__ float g_y[MTOK*DD];

// ======================= helpers ===========================================
__device__ __forceinline__ uint32_t pk(float lo, float hi) {
    uint32_t r; asm("cvt.rn.bf16x2.f32 %0, %1, %2;" : "=r"(r) : "f"(hi), "f"(lo)); return r;
}
__device__ __forceinline__ float ex2(float x) {
    float r; asm("ex2.approx.f32 %0, %1;" : "=f"(r) : "f"(x)); return r;
}
__device__ __forceinline__ uint32_t smem_u32(const void* p) {
    uint32_t a;
    asm("{ .reg .u64 t; cvta.to.shared.u64 t, %1; cvt.u32.u64 %0, t; }" : "=r"(a) : "l"(p));
    return a;
}
__device__ __forceinline__ void mma16(float* d, const uint32_t* a, const uint32_t* b) {
    asm volatile(
        "mma.sync.aligned.m16n8k16.row.col.f32.bf16.bf16.f32 "
        "{%0,%1,%2,%3}, {%4,%5,%6,%7}, {%8,%9}, {%0,%1,%2,%3};"
        : "+f"(d[0]), "+f"(d[1]), "+f"(d[2]), "+f"(d[3])
        : "r"(a[0]), "r"(a[1]), "r"(a[2]), "r"(a[3]), "r"(b[0]), "r"(b[1]));
}
__device__ __forceinline__ void ldsm4(uint32_t* r, uint32_t addr) {
    asm volatile("ldmatrix.sync.aligned.m8n8.x4.shared.b16 {%0,%1,%2,%3}, [%4];"
        : "=r"(r[0]), "=r"(r[1]), "=r"(r[2]), "=r"(r[3]) : "r"(addr));
}
__device__ __forceinline__ void ldsm4t(uint32_t* r, uint32_t addr) {
    asm volatile("ldmatrix.sync.aligned.m8n8.x4.trans.shared.b16 {%0,%1,%2,%3}, [%4];"
        : "=r"(r[0]), "=r"(r[1]), "=r"(r[2]), "=r"(r[3]) : "r"(addr));
}
__device__ __forceinline__ void cpa(uint32_t dst, const void* src) {
    asm volatile("cp.async.ca.shared.global [%0], [%1], 16;" :: "r"(dst), "l"(src) : "memory");
}
#define CP_COMMIT() asm volatile("cp.async.commit_group;" ::: "memory")
#define CP_WAIT(n)  asm volatile("cp.async.wait_group %0;" :: "n"(n) : "memory")

// ============================================================================
// fp32 -> bf16 conversions
// ============================================================================
__global__ __launch_bounds__(256) void cvt_kernel(
    const float* __restrict__ in, __nv_bfloat16* __restrict__ out, int n4)
{
    const int i = blockIdx.x * blockDim.x + threadIdx.x;
    if (i < n4) {
        float4 v = ((const float4*)in)[i];
        uint2 u = { pk(v.x, v.y), pk(v.z, v.w) };
        *(uint2*)(out + (size_t)i * 4) = u;
    }
}

__global__ __launch_bounds__(256) void cvt_w_kernel(
    const float* __restrict__ Wq, const float* __restrict__ Wk,
    const float* __restrict__ Wv, const float* __restrict__ Wo,
    __nv_bfloat16* __restrict__ wqkv, __nv_bfloat16* __restrict__ wo)
{
    const int idx = blockIdx.x * blockDim.x + threadIdx.x;
    const int m = idx >> 16, i = idx & 65535;
    const float* src = (m == 0) ? Wq : (m == 1) ? Wk : (m == 2) ? Wv : Wo;
    __nv_bfloat16* dst = (m < 3) ? (wqkv + (size_t)m * DD * DD) : wo;
    float4 v = ((const float4*)src)[i];
    uint2 u = { pk(v.x, v.y), pk(v.z, v.w) };
    *(uint2*)(dst + (size_t)i * 4) = u;
}

// ============================================================================
// bf16 GEMM mainloop: tile 128x128, BK=64, 8 warps 2(m)x4(n), warp 64x32.
// cp.async 3-stage ring; A and W both row-stride 512.
// ============================================================================
#define GROWB 144
#define GTILE (128*GROWB)
#define G_SMEM (3*2*GTILE)           // 110592

struct GCtx { int m0, n0, wm, wn, g, t, r8, sello, selhi; };

__device__ __forceinline__ void gemm16_mainloop(
    const __nv_bfloat16* __restrict__ A, const __nv_bfloat16* __restrict__ W,
    uint32_t sb, const GCtx& cx, float acc[4][4][4])
{
    const int tid = threadIdx.x;
#pragma unroll
    for (int mt = 0; mt < 4; mt++)
#pragma unroll
        for (int jn = 0; jn < 4; jn++)
#pragma unroll
            for (int e = 0; e < 4; e++) acc[mt][jn][e] = 0.f;

    const int ldrow = tid >> 1;
    const int ldseg = (tid & 1) * 4;

#pragma unroll
    for (int ch = 0; ch < 2; ch++) {
        const uint32_t sA = sb + ch * 2 * GTILE, sW = sA + GTILE;
#pragma unroll
        for (int s = 0; s < 4; s++) {
            cpa(sA + ldrow * GROWB + (ldseg + s) * 16,
                A + (size_t)(cx.m0 + ldrow) * 512 + ch * 64 + (ldseg + s) * 8);
            cpa(sW + ldrow * GROWB + (ldseg + s) * 16,
                W + (size_t)(cx.n0 + ldrow) * 512 + ch * 64 + (ldseg + s) * 8);
        }
        CP_COMMIT();
    }

    for (int ch = 0; ch < 8; ch++) {
        if (ch + 2 < 8) {
            const int nc = ch + 2, st = nc % 3;
            const uint32_t sA = sb + st * 2 * GTILE, sW = sA + GTILE;
#pragma unroll
            for (int s = 0; s < 4; s++) {
                cpa(sA + ldrow * GROWB + (ldseg + s) * 16,
                    A + (size_t)(cx.m0 + ldrow) * 512 + nc * 64 + (ldseg + s) * 8);
                cpa(sW + ldrow * GROWB + (ldseg + s) * 16,
                    W + (size_t)(cx.n0 + ldrow) * 512 + nc * 64 + (ldseg + s) * 8);
            }
            CP_COMMIT();
            CP_WAIT(2);
        } else if (ch + 1 < 8) {
            CP_WAIT(1);
        } else {
            CP_WAIT(0);
        }
        __syncthreads();

        const uint32_t sA = sb + (ch % 3) * 2 * GTILE, sW = sA + GTILE;
#pragma unroll
        for (int ks = 0; ks < 4; ks++) {
            uint32_t af[4][4];
#pragma unroll
            for (int mt = 0; mt < 4; mt++)
                ldsm4(af[mt], sA + (uint32_t)((cx.wm * 64 + mt * 16 + cx.r8 + cx.sello * 8) * GROWB
                                              + (ks * 16 + cx.selhi * 8) * 2));
#pragma unroll
            for (int p = 0; p < 2; p++) {
                uint32_t wf[4];
                ldsm4(wf, sW + (uint32_t)((cx.wn * 32 + p * 16 + cx.r8 + cx.selhi * 8) * GROWB
                                          + (ks * 16 + cx.sello * 8) * 2));
#pragma unroll
                for (int mt = 0; mt < 4; mt++) {
                    mma16(acc[mt][2 * p],     af[mt], wf);
                    mma16(acc[mt][2 * p + 1], af[mt], wf + 2);
                }
            }
        }
        __syncthreads();
    }
}

// Fused QKV: Wqkv[1536][512]; bias/scale routed by column; C stride 1536.
__global__ __launch_bounds__(256, 2) void gemm16_qkv(
    const __nv_bfloat16* __restrict__ A, const __nv_bfloat16* __restrict__ W,
    const float* __restrict__ bq, const float* __restrict__ bk,
    const float* __restrict__ bv, __nv_bfloat16* __restrict__ C)
{
    extern __shared__ __align__(16) char smg[];
    const uint32_t sb = smem_u32(smg);
    const int tid = threadIdx.x, wid = tid >> 5, lane = tid & 31;
    GCtx cx;
    cx.g = lane >> 2; cx.t = lane & 3;
    cx.r8 = lane & 7; cx.sello = (lane >> 3) & 1; cx.selhi = lane >> 4;
    cx.wm = wid >> 2; cx.wn = wid & 3;
    cx.m0 = blockIdx.y * 128; cx.n0 = blockIdx.x * 128;
    float acc[4][4][4];
    gemm16_mainloop(A, W, sb, cx, acc);

    const float* bp = (cx.n0 < 512) ? bq : (cx.n0 < 1024 ? bk : bv);
    const float scale = (cx.n0 < 512) ? QSCALE : 1.f;
#pragma unroll
    for (int mt = 0; mt < 4; mt++) {
#pragma unroll
        for (int jn = 0; jn < 4; jn++) {
            const int row = cx.m0 + cx.wm * 64 + mt * 16 + cx.g;
            const int cg = cx.n0 + cx.wn * 32 + jn * 8 + 2 * cx.t;
            const int cl = cg & 511;
            const float b0 = bp[cl], b1 = bp[cl + 1];
            *(uint32_t*)(C + (size_t)row * QKVD + cg) =
                pk((acc[mt][jn][0] + b0) * scale, (acc[mt][jn][1] + b1) * scale);
            *(uint32_t*)(C + (size_t)(row + 8) * QKVD + cg) =
                pk((acc[mt][jn][2] + b0) * scale, (acc[mt][jn][3] + b1) * scale);
        }
    }
}

// O-proj: fp32 output, acc + bias + residual
__global__ __launch_bounds__(256, 2) void gemm16_f32(
    const __nv_bfloat16* __restrict__ A, const __nv_bfloat16* __restrict__ W,
    const float* __restrict__ bias, const float* __restrict__ res,
    float* __restrict__ C)
{
    extern __shared__ __align__(16) char smg[];
    const uint32_t sb = smem_u32(smg);
    const int tid = threadIdx.x, wid = tid >> 5, lane = tid & 31;
    GCtx cx;
    cx.g = lane >> 2; cx.t = lane & 3;
    cx.r8 = lane & 7; cx.sello = (lane >> 3) & 1; cx.selhi = lane >> 4;
    cx.wm = wid >> 2; cx.wn = wid & 3;
    cx.m0 = blockIdx.y * 128; cx.n0 = blockIdx.x * 128;
    float acc[4][4][4];
    gemm16_mainloop(A, W, sb, cx, acc);

#pragma unroll
    for (int mt = 0; mt < 4; mt++) {
#pragma unroll
        for (int jn = 0; jn < 4; jn++) {
            const int row = cx.m0 + cx.wm * 64 + mt * 16 + cx.g;
            const int col = cx.n0 + cx.wn * 32 + jn * 8 + 2 * cx.t;
            const float b0 = bias[col], b1 = bias[col + 1];
            float2 r0 = *(const float2*)(res + (size_t)row * 512 + col);
            float2 r1 = *(const float2*)(res + (size_t)(row + 8) * 512 + col);
            *(float2*)(C + (size_t)row * 512 + col) =
                make_float2(acc[mt][jn][0] + b0 + r0.x, acc[mt][jn][1] + b1 + r0.y);
            *(float2*)(C + (size_t)(row + 8) * 512 + col) =
                make_float2(acc[mt][jn][2] + b0 + r1.x, acc[mt][jn][3] + b1 + r1.y);
        }
    }
}

// ============================================================================
// bf16 flash attention. 4-warp CTAs: 64 q-rows/block, 64 keys/iter,
// 4 CTAs/SM (launch_bounds(128,4): 4*128*128 = 65536 regs exactly).
// Smaller sync domains; 4 independent CTAs interleave softmax with HMMA.
// Q/K/V from fused qkv (stride 1536). 2-slot cp.async ring, depth-1 prefetch.
// SMEM: Q 64x144=9216; ring 2 x (K 9216 + V 9216) = 36864. Total 46080.
// ============================================================================
#define ROWB 144
#define KVSZ 9216                    // 64 * 144
#define NIT  (SS/64)                 // 32
#define AT_SMEM (9216 + 4*KVSZ)      // 46080
__global__ __launch_bounds__(128, 4) void attn_mma()
{
    extern __shared__ __align__(16) char sm[];
    const uint32_t sb = smem_u32(sm);
    const uint32_t smQ = sb;
    const uint32_t smK0 = sb + 9216, smV0 = sb + 9216 + 2 * KVSZ;

    const int tid = threadIdx.x, wid = tid >> 5, lane = tid & 31;
    const int g = lane >> 2, t = lane & 3;
    const int sel = lane >> 3, r8 = lane & 7;
    const int sello = sel & 1, selhi = sel >> 1;

    const int bh = blockIdx.y;
    const size_t qbase = (size_t)(bh >> 3) * SS * QKVD + (size_t)(bh & 7) * 64;
    const __nv_bfloat16* qp = g_qkv + qbase;
    const __nv_bfloat16* kp = qp + 512;
    const __nv_bfloat16* vp = qp + 1024;
    __nv_bfloat16* op = g_ctx + (size_t)(bh >> 3) * SS * DD + (size_t)(bh & 7) * 64;
    const int q0 = blockIdx.x * 64;
    const int qr = wid * 16;

    // K/V loads: 64 rows x 8 segs; each of 128 threads does 4 consecutive segs
    const int krow = tid >> 1, ks4 = (tid & 1) * 4;

    // ---- prologue: issue K/V tile 0; stage Q ----
    {
#pragma unroll
        for (int s = 0; s < 4; s++) {
            cpa(smK0 + krow * ROWB + (ks4 + s) * 16, kp + (size_t)krow * QKVD + (ks4 + s) * 8);
            cpa(smV0 + krow * ROWB + (ks4 + s) * 16, vp + (size_t)krow * QKVD + (ks4 + s) * 8);
        }
        CP_COMMIT();
    }
#pragma unroll
    for (int it = 0; it < 4; it++) {
        const int lin = tid + 128 * it, row = lin >> 3, seg = lin & 7;
        uint4 u = *(const uint4*)(qp + (size_t)(q0 + row) * QKVD + seg * 8);
        *(uint4*)(sm + row * ROWB + seg * 16) = u;
    }
    __syncthreads();

    uint32_t qf[4][4];
#pragma unroll
    for (int ks = 0; ks < 4; ks++) {
        const uint32_t addr = smQ + (uint32_t)((qr + r8 + sello * 8) * ROWB + (16 * ks + selhi * 8) * 2);
        ldsm4(qf[ks], addr);
    }

    float oacc[8][4];
#pragma unroll
    for (int j = 0; j < 8; j++)
#pragma unroll
        for (int e = 0; e < 4; e++) oacc[j][e] = 0.f;
    float m0r = -1e30f, m1r = -1e30f, l0 = 0.f, l1 = 0.f;

    for (int kb = 0; kb < NIT; kb++) {
        if (kb + 1 < NIT) {
            const int nb = kb + 1;
            const uint32_t dK = smK0 + (nb & 1) * KVSZ, dV = smV0 + (nb & 1) * KVSZ;
#pragma unroll
            for (int s = 0; s < 4; s++) {
                cpa(dK + krow * ROWB + (ks4 + s) * 16,
                    kp + (size_t)(nb * 64 + krow) * QKVD + (ks4 + s) * 8);
                cpa(dV + krow * ROWB + (ks4 + s) * 16,
                    vp + (size_t)(nb * 64 + krow) * QKVD + (ks4 + s) * 8);
            }
            CP_COMMIT();
            CP_WAIT(1);
        } else {
            CP_WAIT(0);
        }
        __syncthreads();

        const uint32_t smK = smK0 + (kb & 1) * KVSZ;
        const uint32_t smV = smV0 + (kb & 1) * KVSZ;

        // ---- S = Q . K^T (16 x 64 per warp) ----
        float sacc[8][4];
#pragma unroll
        for (int j = 0; j < 8; j++)
#pragma unroll
            for (int e = 0; e < 4; e++) sacc[j][e] = 0.f;
#pragma unroll
        for (int ks = 0; ks < 4; ks++) {
#pragma unroll
            for (int jp = 0; jp < 4; jp++) {
                uint32_t kf[4];
                const uint32_t addr = smK + (uint32_t)((jp * 16 + r8 + selhi * 8) * ROWB
                                                       + (16 * ks + sello * 8) * 2);
                ldsm4(kf, addr);
                mma16(sacc[2 * jp],     qf[ks], kf);
                mma16(sacc[2 * jp + 1], qf[ks], kf + 2);
            }
        }

        // ---- warp-local online softmax (base 2) ----
        float mx0 = -1e30f, mx1 = -1e30f;
#pragma unroll
        for (int jn = 0; jn < 8; jn++) {
            mx0 = fmaxf(mx0, fmaxf(sacc[jn][0], sacc[jn][1]));
            mx1 = fmaxf(mx1, fmaxf(sacc[jn][2], sacc[jn][3]));
        }
        mx0 = fmaxf(mx0, __shfl_xor_sync(0xffffffffu, mx0, 1));
        mx0 = fmaxf(mx0, __shfl_xor_sync(0xffffffffu, mx0, 2));
        mx1 = fmaxf(mx1, __shfl_xor_sync(0xffffffffu, mx1, 1));
        mx1 = fmaxf(mx1, __shfl_xor_sync(0xffffffffu, mx1, 2));
        const float mn0 = fmaxf(m0r, mx0), mn1 = fmaxf(m1r, mx1);
        const float c0 = ex2(m0r - mn0), c1 = ex2(m1r - mn1);

        float s0 = 0.f, s1 = 0.f;
#pragma unroll
        for (int jn = 0; jn < 8; jn++) {
            sacc[jn][0] = ex2(sacc[jn][0] - mn0);
            sacc[jn][1] = ex2(sacc[jn][1] - mn0);
            sacc[jn][2] = ex2(sacc[jn][2] - mn1);
            sacc[jn][3] = ex2(sacc[jn][3] - mn1);
            s0 += sacc[jn][0] + sacc[jn][1];
            s1 += sacc[jn][2] + sacc[jn][3];
        }
        s0 += __shfl_xor_sync(0xffffffffu, s0, 1);
        s0 += __shfl_xor_sync(0xffffffffu, s0, 2);
        s1 += __shfl_xor_sync(0xffffffffu, s1, 1);
        s1 += __shfl_xor_sync(0xffffffffu, s1, 2);
        l0 = l0 * c0 + s0; l1 = l1 * c1 + s1;
        m0r = mn0; m1r = mn1;
#pragma unroll
        for (int jd = 0; jd < 8; jd++) {
            oacc[jd][0] *= c0; oacc[jd][1] *= c0;
            oacc[jd][2] *= c1; oacc[jd][3] *= c1;
        }

        // ---- P -> bf16x2 a-fragments (registers only) ----
        uint32_t pf[4][4];
#pragma unroll
        for (int ks = 0; ks < 4; ks++) {
            pf[ks][0] = pk(sacc[2 * ks][0],     sacc[2 * ks][1]);
            pf[ks][1] = pk(sacc[2 * ks][2],     sacc[2 * ks][3]);
            pf[ks][2] = pk(sacc[2 * ks + 1][0], sacc[2 * ks + 1][1]);
            pf[ks][3] = pk(sacc[2 * ks + 1][2], sacc[2 * ks + 1][3]);
        }

        // ---- O += P . V ----
#pragma unroll
        for (int ks = 0; ks < 4; ks++) {
#pragma unroll
            for (int jp = 0; jp < 4; jp++) {
                uint32_t vf[4];
                const uint32_t addr = smV + (uint32_t)((16 * ks + r8 + sello * 8) * ROWB
                                                       + (2 * jp + selhi) * 16);
                ldsm4t(vf, addr);
                mma16(oacc[2 * jp],     pf[ks], vf);
                mma16(oacc[2 * jp + 1], pf[ks], vf + 2);
            }
        }
    }

    const float inv0 = 1.f / l0, inv1 = 1.f / l1;
#pragma unroll
    for (int jd = 0; jd < 8; jd++) {
        const int col = jd * 8 + 2 * t;
        *(uint32_t*)(op + (size_t)(q0 + qr + g) * DD + col) =
            pk(oacc[jd][0] * inv0, oacc[jd][1] * inv0);
        *(uint32_t*)(op + (size_t)(q0 + qr + 8 + g) * DD + col) =
            pk(oacc[jd][2] * inv1, oacc[jd][3] * inv1);
    }
}

// ============================================================================
// LayerNorm: one block (128 thr) per token row of 512
// ============================================================================
__global__ __launch_bounds__(128) void ln_kernel(
    const float* __restrict__ y, const float* __restrict__ gamma,
    const float* __restrict__ beta, float* __restrict__ out)
{
    const int row = blockIdx.x;
    const float* yr = y + (size_t)row * DD;
    float v[4], s = 0.f, s2 = 0.f;
#pragma unroll
    for (int i = 0; i < 4; i++) {
        float x = yr[threadIdx.x + i * 128];
        v[i] = x; s += x; s2 += x * x;
    }
#pragma unroll
    for (int o = 16; o; o >>= 1) {
        s  += __shfl_xor_sync(0xffffffffu, s, o);
        s2 += __shfl_xor_sync(0xffffffffu, s2, o);
    }
    __shared__ float sh[8];
    const int w = threadIdx.x >> 5;
    if ((threadIdx.x & 31) == 0) { sh[w] = s; sh[w + 4] = s2; }
    __syncthreads();
    s  = sh[0] + sh[1] + sh[2] + sh[3];
    s2 = sh[4] + sh[5] + sh[6] + sh[7];
    const float mu   = s * (1.f / DD);
    const float var  = s2 * (1.f / DD) - mu * mu;
    const float rstd = rsqrtf(var + 1e-5f);
    float* orow = out + (size_t)row * DD;
#pragma unroll
    for (int i = 0; i < 4; i++) {
        const int c = threadIdx.x + i * 128;
        orow[c] = (v[i] - mu) * rstd * gamma[c] + beta[c];
    }
}

// ============================================================================
extern "C" void kernel_launch(void* const* d_in, const int* in_sizes, int n_in,
                              void* d_out, int out_size)
{
    const float* x     = (const float*)d_in[0];
    const float* Wq    = (const float*)d_in[1];
    const float* bq    = (const float*)d_in[2];
    const float* Wk    = (const float*)d_in[3];
    const float* bk    = (const float*)d_in[4];
    const float* Wv    = (const float*)d_in[5];
    const float* bv    = (const float*)d_in[6];
    const float* Wo    = (const float*)d_in[7];
    const float* bo    = (const float*)d_in[8];
    const float* gamma = (const float*)d_in[9];
    const float* beta  = (const float*)d_in[10];
    float* out = (float*)d_out;

    __nv_bfloat16 *x16, *wqkv, *wo, *qkv, *cp;
    float *yp;
    cudaGetSymbolAddress((void**)&x16, g_x16);
    cudaGetSymbolAddress((void**)&wqkv, g_wqkv);
    cudaGetSymbolAddress((void**)&wo, g_wo);
    cudaGetSymbolAddress((void**)&qkv, g_qkv);
    cudaGetSymbolAddress((void**)&cp, g_ctx);
    cudaGetSymbolAddress((void**)&yp, g_y);

    cudaFuncSetAttribute(attn_mma, cudaFuncAttributeMaxDynamicSharedMemorySize, AT_SMEM);
    cudaFuncSetAttribute(gemm16_qkv, cudaFuncAttributeMaxDynamicSharedMemorySize, G_SMEM);
    cudaFuncSetAttribute(gemm16_f32, cudaFuncAttributeMaxDynamicSharedMemorySize, G_SMEM);

    // convert x (1 launch) + all weights (1 launch) to bf16
    cvt_kernel<<<(MTOK * DD / 4 + 255) / 256, 256>>>(x, x16, MTOK * DD / 4);
    cvt_w_kernel<<<4 * (DD * DD / 4) / 256, 256>>>(Wq, Wk, Wv, Wo, wqkv, wo);

    // fused QKV projection
    gemm16_qkv<<<dim3(QKVD / 128, MTOK / 128), 256, G_SMEM>>>(x16, wqkv, bq, bk, bv, qkv);

    attn_mma<<<dim3(SS / 64, BB * HH), 128, AT_SMEM>>>();

    gemm16_f32<<<dim3(DD / 128, MTOK / 128), 256, G_SMEM>>>(cp, wo, bo, x, yp);

    ln_kernel<<<MTOK, 128>>>(yp, gamma, beta, out);
}

// round 11
// speedup vs baseline: 1.1301x; 1.1301x over previous
#include <cuda_runtime.h>
#include <cuda_bf16.h>
#include <cstdint>

#define BB 4
#define SS 2048
#define DD 512
#define HH 8
#define MTOK (BB*SS)
#define QKVD 1536
#define QSCALE (0.125f * 1.44269504f)   // 1/sqrt(dk) * log2(e)

// Scratch (module-load allocated; no cudaMalloc anywhere)
__device__ __align__(256) __nv_bfloat16 g_x16[MTOK*DD];
__device__ __align__(256) __nv_bfloat16 g_wqkv[QKVD*DD];
__device__ __align__(256) __nv_bfloat16 g_wo[DD*DD];
__device__ __align__(256) __nv_bfloat16 g_qkv[MTOK*QKVD];
__device__ __align__(256) __nv_bfloat16 g_ctx[MTOK*DD];

// ======================= helpers ===========================================
__device__ __forceinline__ uint32_t pk(float lo, float hi) {
    uint32_t r; asm("cvt.rn.bf16x2.f32 %0, %1, %2;" : "=r"(r) : "f"(hi), "f"(lo)); return r;
}
__device__ __forceinline__ float ex2(float x) {
    float r; asm("ex2.approx.f32 %0, %1;" : "=f"(r) : "f"(x)); return r;
}
__device__ __forceinline__ uint32_t smem_u32(const void* p) {
    uint32_t a;
    asm("{ .reg .u64 t; cvta.to.shared.u64 t, %1; cvt.u32.u64 %0, t; }" : "=r"(a) : "l"(p));
    return a;
}
__device__ __forceinline__ void mma16(float* d, const uint32_t* a, const uint32_t* b) {
    asm volatile(
        "mma.sync.aligned.m16n8k16.row.col.f32.bf16.bf16.f32 "
        "{%0,%1,%2,%3}, {%4,%5,%6,%7}, {%8,%9}, {%0,%1,%2,%3};"
        : "+f"(d[0]), "+f"(d[1]), "+f"(d[2]), "+f"(d[3])
        : "r"(a[0]), "r"(a[1]), "r"(a[2]), "r"(a[3]), "r"(b[0]), "r"(b[1]));
}
__device__ __forceinline__ void ldsm4(uint32_t* r, uint32_t addr) {
    asm volatile("ldmatrix.sync.aligned.m8n8.x4.shared.b16 {%0,%1,%2,%3}, [%4];"
        : "=r"(r[0]), "=r"(r[1]), "=r"(r[2]), "=r"(r[3]) : "r"(addr));
}
__device__ __forceinline__ void ldsm4t(uint32_t* r, uint32_t addr) {
    asm volatile("ldmatrix.sync.aligned.m8n8.x4.trans.shared.b16 {%0,%1,%2,%3}, [%4];"
        : "=r"(r[0]), "=r"(r[1]), "=r"(r[2]), "=r"(r[3]) : "r"(addr));
}
__device__ __forceinline__ void cpa(uint32_t dst, const void* src) {
    asm volatile("cp.async.ca.shared.global [%0], [%1], 16;" :: "r"(dst), "l"(src) : "memory");
}
#define CP_COMMIT() asm volatile("cp.async.commit_group;" ::: "memory")
#define CP_WAIT(n)  asm volatile("cp.async.wait_group %0;" :: "n"(n) : "memory")

// ============================================================================
// fp32 -> bf16: x + all 4 weights in ONE launch
// ============================================================================
#define NX4 (MTOK*DD/4)              // 1048576 float4 in x
#define NW4 (DD*DD/4)                // 65536 float4 per weight
__global__ __launch_bounds__(256) void cvt_all(
    const float* __restrict__ x,
    const float* __restrict__ Wq, const float* __restrict__ Wk,
    const float* __restrict__ Wv, const float* __restrict__ Wo,
    __nv_bfloat16* __restrict__ x16, __nv_bfloat16* __restrict__ wqkv,
    __nv_bfloat16* __restrict__ wo)
{
    const int idx = blockIdx.x * blockDim.x + threadIdx.x;
    const float* src;
    __nv_bfloat16* dst;
    int i;
    if (idx < NX4) {
        src = x; dst = x16; i = idx;
    } else {
        const int j = idx - NX4;
        const int m = j >> 16;
        i = j & 65535;
        src = (m == 0) ? Wq : (m == 1) ? Wk : (m == 2) ? Wv : Wo;
        dst = (m < 3) ? (wqkv + (size_t)m * DD * DD) : wo;
    }
    float4 v = ((const float4*)src)[i];
    uint2 u = { pk(v.x, v.y), pk(v.z, v.w) };
    *(uint2*)(dst + (size_t)i * 4) = u;
}

// ============================================================================
// Fused QKV GEMM: tile 128x128, BK=64, 8 warps 2(m)x4(n), cp.async 3-stage.
// ============================================================================
#define GROWB 144
#define GTILE (128*GROWB)
#define G_SMEM (3*2*GTILE)           // 110592

__global__ __launch_bounds__(256, 2) void gemm16_qkv(
    const __nv_bfloat16* __restrict__ A, const __nv_bfloat16* __restrict__ W,
    const float* __restrict__ bq, const float* __restrict__ bk,
    const float* __restrict__ bv, __nv_bfloat16* __restrict__ C)
{
    extern __shared__ __align__(16) char smg[];
    const uint32_t sb = smem_u32(smg);
    const int tid = threadIdx.x, wid = tid >> 5, lane = tid & 31;
    const int g = lane >> 2, t = lane & 3;
    const int r8 = lane & 7, sello = (lane >> 3) & 1, selhi = lane >> 4;
    const int wm = wid >> 2, wn = wid & 3;
    const int m0 = blockIdx.y * 128, n0 = blockIdx.x * 128;

    float acc[4][4][4];
#pragma unroll
    for (int mt = 0; mt < 4; mt++)
#pragma unroll
        for (int jn = 0; jn < 4; jn++)
#pragma unroll
            for (int e = 0; e < 4; e++) acc[mt][jn][e] = 0.f;

    const int ldrow = tid >> 1, ldseg = (tid & 1) * 4;

#pragma unroll
    for (int ch = 0; ch < 2; ch++) {
        const uint32_t sA = sb + ch * 2 * GTILE, sW = sA + GTILE;
#pragma unroll
        for (int s = 0; s < 4; s++) {
            cpa(sA + ldrow * GROWB + (ldseg + s) * 16,
                A + (size_t)(m0 + ldrow) * 512 + ch * 64 + (ldseg + s) * 8);
            cpa(sW + ldrow * GROWB + (ldseg + s) * 16,
                W + (size_t)(n0 + ldrow) * 512 + ch * 64 + (ldseg + s) * 8);
        }
        CP_COMMIT();
    }

    for (int ch = 0; ch < 8; ch++) {
        if (ch + 2 < 8) {
            const int nc = ch + 2, st = nc % 3;
            const uint32_t sA = sb + st * 2 * GTILE, sW = sA + GTILE;
#pragma unroll
            for (int s = 0; s < 4; s++) {
                cpa(sA + ldrow * GROWB + (ldseg + s) * 16,
                    A + (size_t)(m0 + ldrow) * 512 + nc * 64 + (ldseg + s) * 8);
                cpa(sW + ldrow * GROWB + (ldseg + s) * 16,
                    W + (size_t)(n0 + ldrow) * 512 + nc * 64 + (ldseg + s) * 8);
            }
            CP_COMMIT();
            CP_WAIT(2);
        } else if (ch + 1 < 8) {
            CP_WAIT(1);
        } else {
            CP_WAIT(0);
        }
        __syncthreads();

        const uint32_t sA = sb + (ch % 3) * 2 * GTILE, sW = sA + GTILE;
#pragma unroll
        for (int ks = 0; ks < 4; ks++) {
            uint32_t af[4][4];
#pragma unroll
            for (int mt = 0; mt < 4; mt++)
                ldsm4(af[mt], sA + (uint32_t)((wm * 64 + mt * 16 + r8 + sello * 8) * GROWB
                                              + (ks * 16 + selhi * 8) * 2));
#pragma unroll
            for (int p = 0; p < 2; p++) {
                uint32_t wf[4];
                ldsm4(wf, sW + (uint32_t)((wn * 32 + p * 16 + r8 + selhi * 8) * GROWB
                                          + (ks * 16 + sello * 8) * 2));
#pragma unroll
                for (int mt = 0; mt < 4; mt++) {
                    mma16(acc[mt][2 * p],     af[mt], wf);
                    mma16(acc[mt][2 * p + 1], af[mt], wf + 2);
                }
            }
        }
        __syncthreads();
    }

    const float* bp = (n0 < 512) ? bq : (n0 < 1024 ? bk : bv);
    const float scale = (n0 < 512) ? QSCALE : 1.f;
#pragma unroll
    for (int mt = 0; mt < 4; mt++) {
#pragma unroll
        for (int jn = 0; jn < 4; jn++) {
            const int row = m0 + wm * 64 + mt * 16 + g;
            const int cg = n0 + wn * 32 + jn * 8 + 2 * t;
            const int cl = cg & 511;
            const float b0 = bp[cl], b1 = bp[cl + 1];
            *(uint32_t*)(C + (size_t)row * QKVD + cg) =
                pk((acc[mt][jn][0] + b0) * scale, (acc[mt][jn][1] + b1) * scale);
            *(uint32_t*)(C + (size_t)(row + 8) * QKVD + cg) =
                pk((acc[mt][jn][2] + b0) * scale, (acc[mt][jn][3] + b1) * scale);
        }
    }
}

// ============================================================================
// Fused O-projection + bias + residual + LayerNorm.
// Tile 32 rows x 512 cols (full row per CTA -> in-CTA LayerNorm).
// 8 warps, warp owns 64 cols; acc[2][8][4]. BK=64, 2-stage cp.async ring.
// SMEM/stage: A 32x144=4608, W 512x144=73728 -> 2x78336 = 156672.
// ============================================================================
#define OATILE (32*GROWB)            // 4608
#define OWTILE (512*GROWB)           // 73728
#define OSTAGE (OATILE+OWTILE)       // 78336
#define OLN_SMEM (2*OSTAGE)          // 156672

__global__ __launch_bounds__(256, 1) void gemm16_oln(
    const __nv_bfloat16* __restrict__ A, const __nv_bfloat16* __restrict__ W,
    const float* __restrict__ bias, const float* __restrict__ res,
    const float* __restrict__ gamma, const float* __restrict__ beta,
    float* __restrict__ out)
{
    extern __shared__ __align__(16) char smg[];
    const uint32_t sb = smem_u32(smg);
    const int tid = threadIdx.x, wid = tid >> 5, lane = tid & 31;
    const int g = lane >> 2, t = lane & 3;
    const int r8 = lane & 7, sello = (lane >> 3) & 1, selhi = lane >> 4;
    const int m0 = blockIdx.x * 32;

    float acc[2][8][4];
#pragma unroll
    for (int mt = 0; mt < 2; mt++)
#pragma unroll
        for (int jn = 0; jn < 8; jn++)
#pragma unroll
            for (int e = 0; e < 4; e++) acc[mt][jn][e] = 0.f;

    // A loads: 32 rows x 8 segs = 256 ops (1/thread). W: 512 x 8 = 4096 (16/thread).
    const int arow = tid >> 3, aseg = tid & 7;

#pragma unroll
    for (int ch = 0; ch < 2; ch++) {
        const uint32_t sA = sb + ch * OSTAGE, sW = sA + OATILE;
        cpa(sA + arow * GROWB + aseg * 16, A + (size_t)(m0 + arow) * 512 + ch * 64 + aseg * 8);
#pragma unroll
        for (int w = 0; w < 16; w++) {
            const int lin = tid + 256 * w, row = lin >> 3, seg = lin & 7;
            cpa(sW + row * GROWB + seg * 16, W + (size_t)row * 512 + ch * 64 + seg * 8);
        }
        CP_COMMIT();
    }

    for (int ch = 0; ch < 8; ch++) {
        if (ch + 1 < 8) { CP_WAIT(1); } else { CP_WAIT(0); }
        __syncthreads();

        const uint32_t sA = sb + (ch & 1) * OSTAGE, sW = sA + OATILE;
#pragma unroll
        for (int ks = 0; ks < 4; ks++) {
            uint32_t af[2][4];
#pragma unroll
            for (int mt = 0; mt < 2; mt++)
                ldsm4(af[mt], sA + (uint32_t)((mt * 16 + r8 + sello * 8) * GROWB
                                              + (ks * 16 + selhi * 8) * 2));
#pragma unroll
            for (int jp = 0; jp < 4; jp++) {
                uint32_t wf[4];
                ldsm4(wf, sW + (uint32_t)((wid * 64 + jp * 16 + r8 + selhi * 8) * GROWB
                                          + (ks * 16 + sello * 8) * 2));
#pragma unroll
                for (int mt = 0; mt < 2; mt++) {
                    mma16(acc[mt][2 * jp],     af[mt], wf);
                    mma16(acc[mt][2 * jp + 1], af[mt], wf + 2);
                }
            }
        }
        __syncthreads();

        if (ch + 2 < 8) {
            const int nc = ch + 2;
            const uint32_t sA2 = sb + (ch & 1) * OSTAGE, sW2 = sA2 + OATILE;
            cpa(sA2 + arow * GROWB + aseg * 16,
                A + (size_t)(m0 + arow) * 512 + nc * 64 + aseg * 8);
#pragma unroll
            for (int w = 0; w < 16; w++) {
                const int lin = tid + 256 * w, row = lin >> 3, seg = lin & 7;
                cpa(sW2 + row * GROWB + seg * 16, W + (size_t)row * 512 + nc * 64 + seg * 8);
            }
            CP_COMMIT();
        }
    }

    // ---- epilogue: y = acc + bias + residual; in-CTA LayerNorm ----
    float s[4] = {0.f, 0.f, 0.f, 0.f}, s2[4] = {0.f, 0.f, 0.f, 0.f};
#pragma unroll
    for (int mt = 0; mt < 2; mt++) {
        const int r0 = m0 + mt * 16 + g, r1 = r0 + 8;
#pragma unroll
        for (int jn = 0; jn < 8; jn++) {
            const int col = wid * 64 + jn * 8 + 2 * t;
            const float b0 = bias[col], b1 = bias[col + 1];
            float2 rr0 = *(const float2*)(res + (size_t)r0 * 512 + col);
            float2 rr1 = *(const float2*)(res + (size_t)r1 * 512 + col);
            const float y0 = acc[mt][jn][0] + b0 + rr0.x;
            const float y1 = acc[mt][jn][1] + b1 + rr0.y;
            const float y2 = acc[mt][jn][2] + b0 + rr1.x;
            const float y3 = acc[mt][jn][3] + b1 + rr1.y;
            acc[mt][jn][0] = y0; acc[mt][jn][1] = y1;
            acc[mt][jn][2] = y2; acc[mt][jn][3] = y3;
            s[mt * 2]      += y0 + y1;  s2[mt * 2]      += y0 * y0 + y1 * y1;
            s[mt * 2 + 1]  += y2 + y3;  s2[mt * 2 + 1]  += y2 * y2 + y3 * y3;
        }
    }
#pragma unroll
    for (int i = 0; i < 4; i++) {
        s[i]  += __shfl_xor_sync(0xffffffffu, s[i], 1);
        s[i]  += __shfl_xor_sync(0xffffffffu, s[i], 2);
        s2[i] += __shfl_xor_sync(0xffffffffu, s2[i], 1);
        s2[i] += __shfl_xor_sync(0xffffffffu, s2[i], 2);
    }

    float* SSm = (float*)smg;          // [32][8]
    float* S2m = (float*)(smg + 1024); // [32][8]
    if (t == 0) {
#pragma unroll
        for (int i = 0; i < 4; i++) {
            const int rl = (i >> 1) * 16 + (i & 1) * 8 + g;
            SSm[rl * 8 + wid] = s[i];
            S2m[rl * 8 + wid] = s2[i];
        }
    }
    __syncthreads();

    float mu[4], rstd[4];
#pragma unroll
    for (int i = 0; i < 4; i++) {
        const int rl = (i >> 1) * 16 + (i & 1) * 8 + g;
        float st = 0.f, st2 = 0.f;
#pragma unroll
        for (int w = 0; w < 8; w++) { st += SSm[rl * 8 + w]; st2 += S2m[rl * 8 + w]; }
        mu[i] = st * (1.f / DD);
        rstd[i] = rsqrtf(st2 * (1.f / DD) - mu[i] * mu[i] + 1e-5f);
    }

#pragma unroll
    for (int mt = 0; mt < 2; mt++) {
        const int r0 = m0 + mt * 16 + g, r1 = r0 + 8;
        const int i0 = mt * 2, i1 = mt * 2 + 1;
#pragma unroll
        for (int jn = 0; jn < 8; jn++) {
            const int col = wid * 64 + jn * 8 + 2 * t;
            const float ga0 = gamma[col], ga1 = gamma[col + 1];
            const float be0 = beta[col],  be1 = beta[col + 1];
            *(float2*)(out + (size_t)r0 * 512 + col) = make_float2(
                (acc[mt][jn][0] - mu[i0]) * rstd[i0] * ga0 + be0,
                (acc[mt][jn][1] - mu[i0]) * rstd[i0] * ga1 + be1);
            *(float2*)(out + (size_t)r1 * 512 + col) = make_float2(
                (acc[mt][jn][2] - mu[i1]) * rstd[i1] * ga0 + be0,
                (acc[mt][jn][3] - mu[i1]) * rstd[i1] * ga1 + be1);
        }
    }
}

// ============================================================================
// bf16 flash attention (round-9 proven shape). 128 q-rows/block, 64 keys/iter,
// 8 warps, 2 CTAs/SM. Q/K/V from fused qkv buffer (row stride 1536).
// 4-slot cp.async ring, depth-2 prefetch, one __syncthreads/iter.
// ============================================================================
#define ROWB 144
#define KVSZ 9216                    // 64 * 144
#define NIT  (SS/64)                 // 32
#define AT_SMEM (18432 + 8*KVSZ)     // 92160
__global__ __launch_bounds__(256, 2) void attn_mma()
{
    extern __shared__ __align__(16) char sm[];
    const uint32_t sb = smem_u32(sm);
    const uint32_t smQ = sb;
    const uint32_t smK0 = sb + 18432, smV0 = sb + 18432 + 4 * KVSZ;

    const int tid = threadIdx.x, wid = tid >> 5, lane = tid & 31;
    const int g = lane >> 2, t = lane & 3;
    const int sel = lane >> 3, r8 = lane & 7;
    const int sello = sel & 1, selhi = sel >> 1;

    const int bh = blockIdx.y;
    const size_t qbase = (size_t)(bh >> 3) * SS * QKVD + (size_t)(bh & 7) * 64;
    const __nv_bfloat16* qp = g_qkv + qbase;
    const __nv_bfloat16* kp = qp + 512;
    const __nv_bfloat16* vp = qp + 1024;
    __nv_bfloat16* op = g_ctx + (size_t)(bh >> 3) * SS * DD + (size_t)(bh & 7) * 64;
    const int q0 = blockIdx.x * 128;
    const int qr = wid * 16;

#pragma unroll
    for (int kb = 0; kb < 2; kb++) {
        const uint32_t dK = smK0 + kb * KVSZ, dV = smV0 + kb * KVSZ;
#pragma unroll
        for (int o = 0; o < 2; o++) {
            const int lin = tid + 256 * o, row = lin >> 3, seg = lin & 7;
            cpa(dK + row * ROWB + seg * 16, kp + (size_t)(kb * 64 + row) * QKVD + seg * 8);
            cpa(dV + row * ROWB + seg * 16, vp + (size_t)(kb * 64 + row) * QKVD + seg * 8);
        }
        CP_COMMIT();
    }
#pragma unroll
    for (int it = 0; it < 4; it++) {
        const int lin = tid + 256 * it, row = lin >> 3, seg = lin & 7;
        uint4 u = *(const uint4*)(qp + (size_t)(q0 + row) * QKVD + seg * 8);
        *(uint4*)(sm + row * ROWB + seg * 16) = u;
    }
    __syncthreads();

    uint32_t qf[4][4];
#pragma unroll
    for (int ks = 0; ks < 4; ks++) {
        const uint32_t addr = smQ + (uint32_t)((qr + r8 + sello * 8) * ROWB + (16 * ks + selhi * 8) * 2);
        ldsm4(qf[ks], addr);
    }

    float oacc[8][4];
#pragma unroll
    for (int j = 0; j < 8; j++)
#pragma unroll
        for (int e = 0; e < 4; e++) oacc[j][e] = 0.f;
    float m0r = -1e30f, m1r = -1e30f, l0 = 0.f, l1 = 0.f;

    for (int kb = 0; kb < NIT; kb++) {
        if (kb + 2 < NIT) {
            const int nb = kb + 2;
            const uint32_t dK = smK0 + (nb & 3) * KVSZ, dV = smV0 + (nb & 3) * KVSZ;
#pragma unroll
            for (int o = 0; o < 2; o++) {
                const int lin = tid + 256 * o, row = lin >> 3, seg = lin & 7;
                cpa(dK + row * ROWB + seg * 16, kp + (size_t)(nb * 64 + row) * QKVD + seg * 8);
                cpa(dV + row * ROWB + seg * 16, vp + (size_t)(nb * 64 + row) * QKVD + seg * 8);
            }
            CP_COMMIT();
            CP_WAIT(2);
        } else if (kb + 1 < NIT) {
            CP_WAIT(1);
        } else {
            CP_WAIT(0);
        }
        __syncthreads();

        const uint32_t smK = smK0 + (kb & 3) * KVSZ;
        const uint32_t smV = smV0 + (kb & 3) * KVSZ;

        float sacc[8][4];
#pragma unroll
        for (int j = 0; j < 8; j++)
#pragma unroll
            for (int e = 0; e < 4; e++) sacc[j][e] = 0.f;
#pragma unroll
        for (int ks = 0; ks < 4; ks++) {
#pragma unroll
            for (int jp = 0; jp < 4; jp++) {
                uint32_t kf[4];
                const uint32_t addr = smK + (uint32_t)((jp * 16 + r8 + selhi * 8) * ROWB
                                                       + (16 * ks + sello * 8) * 2);
                ldsm4(kf, addr);
                mma16(sacc[2 * jp],     qf[ks], kf);
                mma16(sacc[2 * jp + 1], qf[ks], kf + 2);
            }
        }

        float mx0 = -1e30f, mx1 = -1e30f;
#pragma unroll
        for (int jn = 0; jn < 8; jn++) {
            mx0 = fmaxf(mx0, fmaxf(sacc[jn][0], sacc[jn][1]));
            mx1 = fmaxf(mx1, fmaxf(sacc[jn][2], sacc[jn][3]));
        }
        mx0 = fmaxf(mx0, __shfl_xor_sync(0xffffffffu, mx0, 1));
        mx0 = fmaxf(mx0, __shfl_xor_sync(0xffffffffu, mx0, 2));
        mx1 = fmaxf(mx1, __shfl_xor_sync(0xffffffffu, mx1, 1));
        mx1 = fmaxf(mx1, __shfl_xor_sync(0xffffffffu, mx1, 2));
        const float mn0 = fmaxf(m0r, mx0), mn1 = fmaxf(m1r, mx1);
        const float c0 = ex2(m0r - mn0), c1 = ex2(m1r - mn1);

        float s0 = 0.f, s1 = 0.f;
#pragma unroll
        for (int jn = 0; jn < 8; jn++) {
            sacc[jn][0] = ex2(sacc[jn][0] - mn0);
            sacc[jn][1] = ex2(sacc[jn][1] - mn0);
            sacc[jn][2] = ex2(sacc[jn][2] - mn1);
            sacc[jn][3] = ex2(sacc[jn][3] - mn1);
            s0 += sacc[jn][0] + sacc[jn][1];
            s1 += sacc[jn][2] + sacc[jn][3];
        }
        s0 += __shfl_xor_sync(0xffffffffu, s0, 1);
        s0 += __shfl_xor_sync(0xffffffffu, s0, 2);
        s1 += __shfl_xor_sync(0xffffffffu, s1, 1);
        s1 += __shfl_xor_sync(0xffffffffu, s1, 2);
        l0 = l0 * c0 + s0; l1 = l1 * c1 + s1;
        m0r = mn0; m1r = mn1;
#pragma unroll
        for (int jd = 0; jd < 8; jd++) {
            oacc[jd][0] *= c0; oacc[jd][1] *= c0;
            oacc[jd][2] *= c1; oacc[jd][3] *= c1;
        }

        uint32_t pf[4][4];
#pragma unroll
        for (int ks = 0; ks < 4; ks++) {
            pf[ks][0] = pk(sacc[2 * ks][0],     sacc[2 * ks][1]);
            pf[ks][1] = pk(sacc[2 * ks][2],     sacc[2 * ks][3]);
            pf[ks][2] = pk(sacc[2 * ks + 1][0], sacc[2 * ks + 1][1]);
            pf[ks][3] = pk(sacc[2 * ks + 1][2], sacc[2 * ks + 1][3]);
        }

#pragma unroll
        for (int ks = 0; ks < 4; ks++) {
#pragma unroll
            for (int jp = 0; jp < 4; jp++) {
                uint32_t vf[4];
                const uint32_t addr = smV + (uint32_t)((16 * ks + r8 + sello * 8) * ROWB
                                                       + (2 * jp + selhi) * 16);
                ldsm4t(vf, addr);
                mma16(oacc[2 * jp],     pf[ks], vf);
                mma16(oacc[2 * jp + 1], pf[ks], vf + 2);
            }
        }
    }

    const float inv0 = 1.f / l0, inv1 = 1.f / l1;
#pragma unroll
    for (int jd = 0; jd < 8; jd++) {
        const int col = jd * 8 + 2 * t;
        *(uint32_t*)(op + (size_t)(q0 + qr + g) * DD + col) =
            pk(oacc[jd][0] * inv0, oacc[jd][1] * inv0);
        *(uint32_t*)(op + (size_t)(q0 + qr + 8 + g) * DD + col) =
            pk(oacc[jd][2] * inv1, oacc[jd][3] * inv1);
    }
}

// ============================================================================
extern "C" void kernel_launch(void* const* d_in, const int* in_sizes, int n_in,
                              void* d_out, int out_size)
{
    const float* x     = (const float*)d_in[0];
    const float* Wq    = (const float*)d_in[1];
    const float* bq    = (const float*)d_in[2];
    const float* Wk    = (const float*)d_in[3];
    const float* bk    = (const float*)d_in[4];
    const float* Wv    = (const float*)d_in[5];
    const float* bv    = (const float*)d_in[6];
    const float* Wo    = (const float*)d_in[7];
    const float* bo    = (const float*)d_in[8];
    const float* gamma = (const float*)d_in[9];
    const float* beta  = (const float*)d_in[10];
    float* out = (float*)d_out;

    __nv_bfloat16 *x16, *wqkv, *wo, *qkv, *cp;
    cudaGetSymbolAddress((void**)&x16, g_x16);
    cudaGetSymbolAddress((void**)&wqkv, g_wqkv);
    cudaGetSymbolAddress((void**)&wo, g_wo);
    cudaGetSymbolAddress((void**)&qkv, g_qkv);
    cudaGetSymbolAddress((void**)&cp, g_ctx);

    cudaFuncSetAttribute(attn_mma, cudaFuncAttributeMaxDynamicSharedMemorySize, AT_SMEM);
    cudaFuncSetAttribute(gemm16_qkv, cudaFuncAttributeMaxDynamicSharedMemorySize, G_SMEM);
    cudaFuncSetAttribute(gemm16_oln, cudaFuncAttributeMaxDynamicSharedMemorySize, OLN_SMEM);

    // one conversion launch: x + all 4 weights
    cvt_all<<<(NX4 + 4 * NW4) / 256, 256>>>(x, Wq, Wk, Wv, Wo, x16, wqkv, wo);

    // fused QKV projection
    gemm16_qkv<<<dim3(QKVD / 128, MTOK / 128), 256, G_SMEM>>>(x16, wqkv, bq, bk, bv, qkv);

    attn_mma<<<dim3(SS / 128, BB * HH), 256, AT_SMEM>>>();

    // fused O-projection + residual + LayerNorm
    gemm16_oln<<<MTOK / 32, 256, OLN_SMEM>>>(cp, wo, bo, x, gamma, beta, out);
}